// round 15
// baseline (speedup 1.0000x reference)
#include <cuda_runtime.h>
#include <cuda_fp16.h>
#include <cstdint>

// Fused int4-dequant + GEMM via mma.sync.m16n8k16 f32-acc (base ISA; tcgen05
// unavailable through the harness's compute_103 PTX path).
// R14: R13's schedule (distributed LDSM/cp.async, cross-stage fragment
// prefetch) on 64x64 warp tiles (4 warps, 128 threads, 2 CTA/SM). Cuts smem
// reads 96->64KB per CTA-stage (A and B replication both 2x), dropping the
// crossbar below the tensor-pipe demand (R13: both co-saturated at ~72-79%).

#define MM   8192
#define NN   4096
#define KK   4096
#define NGRP 32
#define KW   512

#define BM 128
#define BN 128
#define BK 64
#define NSTG 3
#define PITCH 72                        // halfs per row: 128B data + 16B pad
#define TILE_HALFS (128 * PITCH)        // 9216 halfs = 18432 B
#define STAGE_HALFS (2 * TILE_HALFS)    // A + B
#define SMEM_BYTES (NSTG * STAGE_HALFS * 2)   // 110592
#define NKITER (KK / BK)                // 64

// ---------------- device scratch ----------------
__device__ __half g_xh[(size_t)MM * KK];
__device__ __half g_wh[(size_t)NN * KK];

__device__ __forceinline__ uint32_t smem_u32(const void* p) {
    return (uint32_t)__cvta_generic_to_shared(p);
}

#define LDSM_X4(r, addr) \
    asm volatile("ldmatrix.sync.aligned.m8n8.x4.shared.b16 {%0,%1,%2,%3}, [%4];" \
                 : "=r"((r)[0]), "=r"((r)[1]), "=r"((r)[2]), "=r"((r)[3]) \
                 : "r"(addr))

#define MMA16816(c, a, b0, b1) \
    asm volatile("mma.sync.aligned.m16n8k16.row.col.f32.f16.f16.f32 " \
                 "{%0,%1,%2,%3}, {%4,%5,%6,%7}, {%8,%9}, {%0,%1,%2,%3};" \
                 : "+f"((c)[0]), "+f"((c)[1]), "+f"((c)[2]), "+f"((c)[3]) \
                 : "r"((a)[0]), "r"((a)[1]), "r"((a)[2]), "r"((a)[3]), \
                   "r"(b0), "r"(b1))

#define CP16(dst, src) \
    asm volatile("cp.async.cg.shared.global [%0], [%1], 16;" :: "r"(dst), "l"(src))

// ---------------- fused prep: round x + dequant W ----------------
#define XBLOCKS 16384                   // MM*KK / 2048
__global__ void __launch_bounds__(256) prep_kernel(const float* __restrict__ x,
                                                   const int* __restrict__ qw,
                                                   const float* __restrict__ sc,
                                                   const float* __restrict__ zp) {
    if (blockIdx.x < XBLOCKS) {
        size_t i = ((size_t)blockIdx.x * 256 + threadIdx.x) * 8;
        float4 v0 = *(const float4*)(x + i);
        float4 v1 = *(const float4*)(x + i + 4);
        float f[8] = {v0.x, v0.y, v0.z, v0.w, v1.x, v1.y, v1.z, v1.w};
        __half h[8];
#pragma unroll
        for (int j = 0; j < 8; j++) h[j] = __float2half_rn(f[j]);
        *(uint4*)(g_xh + i) = *(const uint4*)h;
    } else {
        int idx = (blockIdx.x - XBLOCKS) * 256 + threadIdx.x;   // word index
        int n = idx >> 9;
        int w = idx & 511;
        unsigned word = ((const unsigned*)qw)[idx];
        int g = w >> 4;
        float s = sc[n * NGRP + g];
        float z = zp[n * NGRP + g];
        __half o[8];
#pragma unroll
        for (int i = 0; i < 8; i++) {
            float q = (float)((word >> (4 * i)) & 0xF);
            o[i] = __float2half_rn(s * (q - z));
        }
        *(uint4*)(g_wh + (size_t)n * KK + w * 8) = *(const uint4*)o;
    }
}

// ---------------- GEMM: 128 threads, 4 warps of 64x64 ----------------
__global__ void __launch_bounds__(128, 2)
gemm_fp16_kernel(const float* __restrict__ bias, float* __restrict__ out) {
    extern __shared__ __half sm[];
    const int tid = threadIdx.x;
    const int wid = tid >> 5;
    const int lane = tid & 31;
    const int warp_m = wid >> 1;       // 0..1 -> 64 rows
    const int warp_n = wid & 1;        // 0..1 -> 64 cols
    const int m0 = blockIdx.y * BM;
    const int n0 = blockIdx.x * BN;

    float acc[4][8][4];
#pragma unroll
    for (int i = 0; i < 4; i++)
#pragma unroll
        for (int j = 0; j < 8; j++)
#pragma unroll
            for (int r = 0; r < 4; r++) acc[i][j][r] = 0.f;

    // ---- loader constants (per thread; 128 threads) ----
    const int lrow = tid >> 3;         // 0..15
    const int lc = tid & 7;            // 0..7
    const uint32_t woff = (uint32_t)(lrow * PITCH + lc * 8) * 2;
    const __half* gA = g_xh + (size_t)(m0 + lrow) * KK + lc * 8;
    const __half* gB = g_wh + (size_t)(n0 + lrow) * KK + lc * 8;

    const uint32_t sbase = smem_u32(sm);
    const uint32_t stA0 = sbase;
    const uint32_t stA1 = sbase + STAGE_HALFS * 2;
    const uint32_t stA2 = sbase + STAGE_HALFS * 4;

    // piece i_: rows [i_*32, i_*32+32) of both tiles; 4 CP16 per thread
#define LOAD_PIECE(wb, i_)                                                    \
    do {                                                                      \
        uint32_t d0_ = (wb) + woff + (uint32_t)(i_ * 32 * PITCH * 2);         \
        uint32_t d1_ = d0_ + (uint32_t)(16 * PITCH * 2);                      \
        CP16(d0_, gA + (size_t)(i_ * 32) * KK);                               \
        CP16(d0_ + TILE_HALFS * 2, gB + (size_t)(i_ * 32) * KK);              \
        CP16(d1_, gA + (size_t)(i_ * 32 + 16) * KK);                          \
        CP16(d1_ + TILE_HALFS * 2, gB + (size_t)(i_ * 32 + 16) * KK);         \
    } while (0)

#define LOAD_STAGE_FULL(wb)                                                   \
    do {                                                                      \
        LOAD_PIECE(wb, 0); LOAD_PIECE(wb, 1);                                 \
        LOAD_PIECE(wb, 2); LOAD_PIECE(wb, 3);                                 \
        asm volatile("cp.async.commit_group;");                               \
        gA += BK; gB += BK;                                                   \
    } while (0)

    LOAD_STAGE_FULL(stA0);
    LOAD_STAGE_FULL(stA1);

    const int lrow16 = lane & 15;
    const int lk16 = (lane >> 4) * 16;
    const uint32_t a_ro = (uint32_t)((warp_m * 64 + lrow16) * PITCH) * 2 + lk16;
    const uint32_t b_ro = (uint32_t)((warp_n * 64 + lrow16) * PITCH) * 2 + lk16 + TILE_HALFS * 2;

    uint32_t ah[2][4][4], bb[2][4][4];

    // 8 MMAs for one (cur, mi) group: B groups bb[cur][0..3] cover 64 cols
#define MMA_GROUP(cur_, mi_)                                                  \
    do {                                                                      \
        _Pragma("unroll")                                                     \
        for (int nj_ = 0; nj_ < 8; nj_++) {                                   \
            uint32_t b0_ = bb[cur_][nj_ >> 1][nj_ & 1];                       \
            uint32_t b1_ = bb[cur_][nj_ >> 1][(nj_ & 1) + 2];                 \
            MMA16816(acc[mi_][nj_], ah[cur_][mi_], b0_, b1_);                 \
        }                                                                     \
    } while (0)

    // One stage; entry invariant: ks=0 frags already in buffers' slot 0.
#define STAGE_BODY(curb, nextb, loadb, do_load, pf_next, waitn)               \
    do {                                                                      \
        const uint32_t sA_ = (curb) + a_ro;                                   \
        const uint32_t sB_ = (curb) + b_ro;                                   \
        _Pragma("unroll")                                                     \
        for (int ks_ = 0; ks_ < 3; ks_++) {                                   \
            const int cur_ = ks_ & 1;                                         \
            const int nxt_ = cur_ ^ 1;                                        \
            const uint32_t kb_ = (uint32_t)((ks_ + 1) * 32);                  \
            LDSM_X4(ah[nxt_][0], sA_ + kb_);                                  \
            LDSM_X4(bb[nxt_][0], sB_ + kb_);                                  \
            MMA_GROUP(cur_, 0);                                               \
            LDSM_X4(ah[nxt_][1], sA_ + (uint32_t)(16 * PITCH * 2) + kb_);     \
            LDSM_X4(bb[nxt_][1], sB_ + (uint32_t)(16 * PITCH * 2) + kb_);     \
            MMA_GROUP(cur_, 1);                                               \
            LDSM_X4(ah[nxt_][2], sA_ + (uint32_t)(32 * PITCH * 2) + kb_);     \
            LDSM_X4(bb[nxt_][2], sB_ + (uint32_t)(32 * PITCH * 2) + kb_);     \
            if (do_load) LOAD_PIECE(loadb, ks_);                              \
            MMA_GROUP(cur_, 2);                                               \
            LDSM_X4(ah[nxt_][3], sA_ + (uint32_t)(48 * PITCH * 2) + kb_);     \
            LDSM_X4(bb[nxt_][3], sB_ + (uint32_t)(48 * PITCH * 2) + kb_);     \
            MMA_GROUP(cur_, 3);                                               \
        }                                                                     \
        if (do_load) {                                                        \
            LOAD_PIECE(loadb, 3);                                             \
            asm volatile("cp.async.commit_group;");                           \
            gA += BK; gB += BK;                                               \
        }                                                                     \
        asm volatile("cp.async.wait_group " #waitn ";" ::: "memory");         \
        __syncthreads();                                                      \
        if (pf_next) {                                                        \
            const uint32_t nA_ = (nextb) + a_ro;                              \
            const uint32_t nB_ = (nextb) + b_ro;                              \
            LDSM_X4(ah[0][0], nA_);                                           \
            LDSM_X4(bb[0][0], nB_);                                           \
            MMA_GROUP(1, 0);                                                  \
            LDSM_X4(ah[0][1], nA_ + (uint32_t)(16 * PITCH * 2));              \
            LDSM_X4(bb[0][1], nB_ + (uint32_t)(16 * PITCH * 2));              \
            MMA_GROUP(1, 1);                                                  \
            LDSM_X4(ah[0][2], nA_ + (uint32_t)(32 * PITCH * 2));              \
            LDSM_X4(bb[0][2], nB_ + (uint32_t)(32 * PITCH * 2));              \
            MMA_GROUP(1, 2);                                                  \
            LDSM_X4(ah[0][3], nA_ + (uint32_t)(48 * PITCH * 2));              \
            LDSM_X4(bb[0][3], nB_ + (uint32_t)(48 * PITCH * 2));              \
            MMA_GROUP(1, 3);                                                  \
        } else {                                                              \
            MMA_GROUP(1, 0); MMA_GROUP(1, 1);                                 \
            MMA_GROUP(1, 2); MMA_GROUP(1, 3);                                 \
        }                                                                     \
    } while (0)

    // prologue
    asm volatile("cp.async.wait_group 1;" ::: "memory");
    __syncthreads();
#pragma unroll
    for (int mi = 0; mi < 4; mi++)
        LDSM_X4(ah[0][mi], stA0 + a_ro + (uint32_t)(mi * 16 * PITCH * 2));
#pragma unroll
    for (int ng = 0; ng < 4; ng++)
        LDSM_X4(bb[0][ng], stA0 + b_ro + (uint32_t)(ng * 16 * PITCH * 2));

    for (int t = 0; t < 20; t++) {
        STAGE_BODY(stA0, stA1, stA2, true, true, 1);   // s = 3t
        STAGE_BODY(stA1, stA2, stA0, true, true, 1);   // s = 3t+1
        STAGE_BODY(stA2, stA0, stA1, true, true, 1);   // s = 3t+2
    }
    STAGE_BODY(stA0, stA1, stA2, true,  true, 1);      // s = 60
    STAGE_BODY(stA1, stA2, stA0, true,  true, 1);      // s = 61
    STAGE_BODY(stA2, stA0, stA1, false, true, 0);      // s = 62
    STAGE_BODY(stA0, stA1, stA2, false, false, 0);     // s = 63

    // ---------------- epilogue ----------------
    const int rb = lane >> 2;
    const int cb = (lane & 3) * 2;
#pragma unroll
    for (int mi = 0; mi < 4; mi++) {
        int m = m0 + warp_m * 64 + mi * 16 + rb;
#pragma unroll
        for (int nj = 0; nj < 8; nj++) {
            int n = n0 + warp_n * 64 + nj * 8 + cb;
            float2 bv = *(const float2*)(bias + n);
            float2 o0, o1;
            o0.x = acc[mi][nj][0] + bv.x;
            o0.y = acc[mi][nj][1] + bv.y;
            o1.x = acc[mi][nj][2] + bv.x;
            o1.y = acc[mi][nj][3] + bv.y;
            *(float2*)(out + (size_t)m * NN + n) = o0;
            *(float2*)(out + (size_t)(m + 8) * NN + n) = o1;
        }
    }
}

// ---------------- launch ----------------
extern "C" void kernel_launch(void* const* d_in, const int* in_sizes, int n_in,
                              void* d_out, int out_size) {
    const float* x    = (const float*)d_in[0];
    const int*   qw   = (const int*)d_in[1];
    const float* sc   = (const float*)d_in[2];
    const float* zp   = (const float*)d_in[3];
    const float* bias = (const float*)d_in[4];
    float* out = (float*)d_out;

    cudaFuncSetAttribute(gemm_fp16_kernel,
                         cudaFuncAttributeMaxDynamicSharedMemorySize, SMEM_BYTES);

    prep_kernel<<<XBLOCKS + (NN * KW) / 256, 256>>>(x, qw, sc, zp);
    gemm_fp16_kernel<<<dim3(NN / BN, MM / BM), 128, SMEM_BYTES>>>(bias, out);
}

// round 16
// speedup vs baseline: 1.0035x; 1.0035x over previous
#include <cuda_runtime.h>
#include <cuda_fp16.h>
#include <cstdint>

// Fused int4-dequant + GEMM via mma.sync.m16n8k16 f32-acc (base ISA; tcgen05
// unavailable through the harness's compute_103 PTX path).
// R15: R14 + immediate-offset addressing. All LDSM / cp.async smem addresses
// are [base_reg + literal] ("n" constraints, hand-unrolled ks blocks), so the
// steady-state loop carries no IMAD/IADD address math (alu was 19%, IMAD on
// the fma pipe 9.4% — issue slots stolen ahead of dependent LDSMs).

#define MM   8192
#define NN   4096
#define KK   4096
#define NGRP 32
#define KW   512

#define BM 128
#define BN 128
#define BK 64
#define NSTG 3
#define PITCH 72                        // halfs per row: 128B data + 16B pad
#define TILE_HALFS (128 * PITCH)        // 9216 halfs = 18432 B
#define STAGE_HALFS (2 * TILE_HALFS)    // A + B
#define SMEM_BYTES (NSTG * STAGE_HALFS * 2)   // 110592
#define NKITER (KK / BK)                // 64
#define ROWB 2304                       // 16 * PITCH * 2 bytes (16 rows)
#define TILEB 18432                     // TILE_HALFS * 2 bytes

// ---------------- device scratch ----------------
__device__ __half g_xh[(size_t)MM * KK];
__device__ __half g_wh[(size_t)NN * KK];

__device__ __forceinline__ uint32_t smem_u32(const void* p) {
    return (uint32_t)__cvta_generic_to_shared(p);
}

#define LDSM_X4I(r, base, imm) \
    asm volatile("ldmatrix.sync.aligned.m8n8.x4.shared.b16 {%0,%1,%2,%3}, [%4+%5];" \
                 : "=r"((r)[0]), "=r"((r)[1]), "=r"((r)[2]), "=r"((r)[3]) \
                 : "r"(base), "n"(imm))

#define MMA16816(c, a, b0, b1) \
    asm volatile("mma.sync.aligned.m16n8k16.row.col.f32.f16.f16.f32 " \
                 "{%0,%1,%2,%3}, {%4,%5,%6,%7}, {%8,%9}, {%0,%1,%2,%3};" \
                 : "+f"((c)[0]), "+f"((c)[1]), "+f"((c)[2]), "+f"((c)[3]) \
                 : "r"((a)[0]), "r"((a)[1]), "r"((a)[2]), "r"((a)[3]), \
                   "r"(b0), "r"(b1))

#define CP16I(base, imm, src) \
    asm volatile("cp.async.cg.shared.global [%0+%1], [%2], 16;" \
                 :: "r"(base), "n"(imm), "l"(src))

// ---------------- fused prep: round x + dequant W ----------------
#define XBLOCKS 16384                   // MM*KK / 2048
__global__ void __launch_bounds__(256) prep_kernel(const float* __restrict__ x,
                                                   const int* __restrict__ qw,
                                                   const float* __restrict__ sc,
                                                   const float* __restrict__ zp) {
    if (blockIdx.x < XBLOCKS) {
        size_t i = ((size_t)blockIdx.x * 256 + threadIdx.x) * 8;
        float4 v0 = *(const float4*)(x + i);
        float4 v1 = *(const float4*)(x + i + 4);
        float f[8] = {v0.x, v0.y, v0.z, v0.w, v1.x, v1.y, v1.z, v1.w};
        __half h[8];
#pragma unroll
        for (int j = 0; j < 8; j++) h[j] = __float2half_rn(f[j]);
        *(uint4*)(g_xh + i) = *(const uint4*)h;
    } else {
        int idx = (blockIdx.x - XBLOCKS) * 256 + threadIdx.x;   // word index
        int n = idx >> 9;
        int w = idx & 511;
        unsigned word = ((const unsigned*)qw)[idx];
        int g = w >> 4;
        float s = sc[n * NGRP + g];
        float z = zp[n * NGRP + g];
        __half o[8];
#pragma unroll
        for (int i = 0; i < 8; i++) {
            float q = (float)((word >> (4 * i)) & 0xF);
            o[i] = __float2half_rn(s * (q - z));
        }
        *(uint4*)(g_wh + (size_t)n * KK + w * 8) = *(const uint4*)o;
    }
}

// ---------------- GEMM: 128 threads, 4 warps of 64x64 ----------------
__global__ void __launch_bounds__(128, 2)
gemm_fp16_kernel(const float* __restrict__ bias, float* __restrict__ out) {
    extern __shared__ __half sm[];
    const int tid = threadIdx.x;
    const int wid = tid >> 5;
    const int lane = tid & 31;
    const int warp_m = wid >> 1;       // 0..1 -> 64 rows
    const int warp_n = wid & 1;        // 0..1 -> 64 cols
    const int m0 = blockIdx.y * BM;
    const int n0 = blockIdx.x * BN;

    float acc[4][8][4];
#pragma unroll
    for (int i = 0; i < 4; i++)
#pragma unroll
        for (int j = 0; j < 8; j++)
#pragma unroll
            for (int r = 0; r < 4; r++) acc[i][j][r] = 0.f;

    // ---- loader constants (per thread; 128 threads) ----
    const int lrow = tid >> 3;         // 0..15
    const int lc = tid & 7;            // 0..7
    const uint32_t woff = (uint32_t)(lrow * PITCH + lc * 8) * 2;
    const __half* gA = g_xh + (size_t)(m0 + lrow) * KK + lc * 8;
    const __half* gB = g_wh + (size_t)(n0 + lrow) * KK + lc * 8;

    const uint32_t sbase = smem_u32(sm);

    const int lrow16 = lane & 15;
    const int lk16 = (lane >> 4) * 16;
    const uint32_t a_ro = (uint32_t)((warp_m * 64 + lrow16) * PITCH) * 2 + lk16;
    const uint32_t b_ro = (uint32_t)((warp_n * 64 + lrow16) * PITCH) * 2 + lk16 + TILEB;

    // precomputed base registers: zero runtime address math in the loop
    const uint32_t aB0 = sbase + a_ro;
    const uint32_t bB0 = sbase + b_ro;
    const uint32_t aB1 = aB0 + STAGE_HALFS * 2;
    const uint32_t bB1 = bB0 + STAGE_HALFS * 2;
    const uint32_t aB2 = aB1 + STAGE_HALFS * 2;
    const uint32_t bB2 = bB1 + STAGE_HALFS * 2;
    const uint32_t wB0 = sbase + woff;
    const uint32_t wB1 = wB0 + STAGE_HALFS * 2;
    const uint32_t wB2 = wB1 + STAGE_HALFS * 2;

    // piece i_ (literal 0..3): rows [i_*32, i_*32+32) of A and B tiles
#define LOAD_PIECE(wb, i_)                                                    \
    do {                                                                      \
        CP16I(wb, (i_) * 4608,                 gA + (size_t)((i_) * 32) * KK); \
        CP16I(wb, (i_) * 4608 + TILEB,         gB + (size_t)((i_) * 32) * KK); \
        CP16I(wb, (i_) * 4608 + ROWB,          gA + (size_t)((i_) * 32 + 16) * KK); \
        CP16I(wb, (i_) * 4608 + ROWB + TILEB,  gB + (size_t)((i_) * 32 + 16) * KK); \
    } while (0)

#define LOAD_STAGE_FULL(wb)                                                   \
    do {                                                                      \
        LOAD_PIECE(wb, 0); LOAD_PIECE(wb, 1);                                 \
        LOAD_PIECE(wb, 2); LOAD_PIECE(wb, 3);                                 \
        asm volatile("cp.async.commit_group;");                               \
        gA += BK; gB += BK;                                                   \
    } while (0)

    LOAD_STAGE_FULL(wB0);
    LOAD_STAGE_FULL(wB1);

    uint32_t ah[2][4][4], bb[2][4][4];

#define MMA_GROUP(cur_, mi_)                                                  \
    do {                                                                      \
        _Pragma("unroll")                                                     \
        for (int nj_ = 0; nj_ < 8; nj_++) {                                   \
            uint32_t b0_ = bb[cur_][nj_ >> 1][nj_ & 1];                       \
            uint32_t b1_ = bb[cur_][nj_ >> 1][(nj_ & 1) + 2];                 \
            MMA16816(acc[mi_][nj_], ah[cur_][mi_], b0_, b1_);                 \
        }                                                                     \
    } while (0)

    // one k16 block; KB/CUR/NXT/PIECE are literals
#define KS_BLOCK(aC, bC, wL, do_load, KB, CUR, NXT, PIECE)                    \
    do {                                                                      \
        LDSM_X4I(ah[NXT][0], aC, KB);                                         \
        LDSM_X4I(bb[NXT][0], bC, KB);                                         \
        MMA_GROUP(CUR, 0);                                                    \
        LDSM_X4I(ah[NXT][1], aC, ROWB + KB);                                  \
        LDSM_X4I(bb[NXT][1], bC, ROWB + KB);                                  \
        MMA_GROUP(CUR, 1);                                                    \
        LDSM_X4I(ah[NXT][2], aC, 2 * ROWB + KB);                              \
        LDSM_X4I(bb[NXT][2], bC, 2 * ROWB + KB);                              \
        if (do_load) LOAD_PIECE(wL, PIECE);                                   \
        MMA_GROUP(CUR, 2);                                                    \
        LDSM_X4I(ah[NXT][3], aC, 3 * ROWB + KB);                              \
        LDSM_X4I(bb[NXT][3], bC, 3 * ROWB + KB);                              \
        MMA_GROUP(CUR, 3);                                                    \
    } while (0)

    // One stage; entry invariant: ks=0 frags already in slot 0.
#define STAGE_BODY(aC, bC, aN, bN, wL, do_load, pf_next, waitn)               \
    do {                                                                      \
        KS_BLOCK(aC, bC, wL, do_load, 32, 0, 1, 0);                           \
        KS_BLOCK(aC, bC, wL, do_load, 64, 1, 0, 1);                           \
        KS_BLOCK(aC, bC, wL, do_load, 96, 0, 1, 2);                           \
        if (do_load) {                                                        \
            LOAD_PIECE(wL, 3);                                                \
            asm volatile("cp.async.commit_group;");                           \
            gA += BK; gB += BK;                                               \
        }                                                                     \
        asm volatile("cp.async.wait_group " #waitn ";" ::: "memory");         \
        __syncthreads();                                                      \
        if (pf_next) {                                                        \
            LDSM_X4I(ah[0][0], aN, 0);                                        \
            LDSM_X4I(bb[0][0], bN, 0);                                        \
            MMA_GROUP(1, 0);                                                  \
            LDSM_X4I(ah[0][1], aN, ROWB);                                     \
            LDSM_X4I(bb[0][1], bN, ROWB);                                     \
            MMA_GROUP(1, 1);                                                  \
            LDSM_X4I(ah[0][2], aN, 2 * ROWB);                                 \
            LDSM_X4I(bb[0][2], bN, 2 * ROWB);                                 \
            MMA_GROUP(1, 2);                                                  \
            LDSM_X4I(ah[0][3], aN, 3 * ROWB);                                 \
            LDSM_X4I(bb[0][3], bN, 3 * ROWB);                                 \
            MMA_GROUP(1, 3);                                                  \
        } else {                                                              \
            MMA_GROUP(1, 0); MMA_GROUP(1, 1);                                 \
            MMA_GROUP(1, 2); MMA_GROUP(1, 3);                                 \
        }                                                                     \
    } while (0)

    // prologue
    asm volatile("cp.async.wait_group 1;" ::: "memory");
    __syncthreads();
    LDSM_X4I(ah[0][0], aB0, 0);
    LDSM_X4I(ah[0][1], aB0, ROWB);
    LDSM_X4I(ah[0][2], aB0, 2 * ROWB);
    LDSM_X4I(ah[0][3], aB0, 3 * ROWB);
    LDSM_X4I(bb[0][0], bB0, 0);
    LDSM_X4I(bb[0][1], bB0, ROWB);
    LDSM_X4I(bb[0][2], bB0, 2 * ROWB);
    LDSM_X4I(bb[0][3], bB0, 3 * ROWB);

    for (int t = 0; t < 20; t++) {
        STAGE_BODY(aB0, bB0, aB1, bB1, wB2, true, true, 1);   // s = 3t
        STAGE_BODY(aB1, bB1, aB2, bB2, wB0, true, true, 1);   // s = 3t+1
        STAGE_BODY(aB2, bB2, aB0, bB0, wB1, true, true, 1);   // s = 3t+2
    }
    STAGE_BODY(aB0, bB0, aB1, bB1, wB2, true,  true, 1);      // s = 60
    STAGE_BODY(aB1, bB1, aB2, bB2, wB0, true,  true, 1);      // s = 61
    STAGE_BODY(aB2, bB2, aB0, bB0, wB1, false, true, 0);      // s = 62
    STAGE_BODY(aB0, bB0, aB1, bB1, wB2, false, false, 0);     // s = 63

    // ---------------- epilogue ----------------
    const int rb = lane >> 2;
    const int cb = (lane & 3) * 2;
#pragma unroll
    for (int mi = 0; mi < 4; mi++) {
        int m = m0 + warp_m * 64 + mi * 16 + rb;
#pragma unroll
        for (int nj = 0; nj < 8; nj++) {
            int n = n0 + warp_n * 64 + nj * 8 + cb;
            float2 bv = *(const float2*)(bias + n);
            float2 o0, o1;
            o0.x = acc[mi][nj][0] + bv.x;
            o0.y = acc[mi][nj][1] + bv.y;
            o1.x = acc[mi][nj][2] + bv.x;
            o1.y = acc[mi][nj][3] + bv.y;
            *(float2*)(out + (size_t)m * NN + n) = o0;
            *(float2*)(out + (size_t)(m + 8) * NN + n) = o1;
        }
    }
}

// ---------------- launch ----------------
extern "C" void kernel_launch(void* const* d_in, const int* in_sizes, int n_in,
                              void* d_out, int out_size) {
    const float* x    = (const float*)d_in[0];
    const int*   qw   = (const int*)d_in[1];
    const float* sc   = (const float*)d_in[2];
    const float* zp   = (const float*)d_in[3];
    const float* bias = (const float*)d_in[4];
    float* out = (float*)d_out;

    cudaFuncSetAttribute(gemm_fp16_kernel,
                         cudaFuncAttributeMaxDynamicSharedMemorySize, SMEM_BYTES);

    prep_kernel<<<XBLOCKS + (NN * KW) / 256, 256>>>(x, qw, sc, zp);
    gemm_fp16_kernel<<<dim3(NN / BN, MM / BM), 128, SMEM_BYTES>>>(bias, out);
}